// round 1
// baseline (speedup 1.0000x reference)
#include <cuda_runtime.h>
#include <cuda_bf16.h>
#include <math.h>

// Problem constants (fixed-shape problem)
#define NMAX 50000
#define EMAX 1250000
#define LAT 64
#define HID 128
#define STEPS 5
#define EPSV 1e-6f

// ---------------- scratch (device globals; no allocation allowed) ----------------
__device__ float g_elat[(size_t)EMAX * LAT];     // 320 MB edge latents
__device__ float g_nlatA[(size_t)NMAX * LAT];
__device__ float g_nlatB[(size_t)NMAX * LAT];
__device__ float g_x[(size_t)NMAX * LAT];
__device__ int   g_counts[NMAX];
__device__ int   g_off[NMAX];
__device__ int   g_pos[NMAX];
__device__ int   g_eperm[EMAX];
__device__ int   g_sperm[EMAX];

// ---------------- CSR build ----------------
__global__ void zero_counts_kernel(int* counts, int n) {
    int i = blockIdx.x * blockDim.x + threadIdx.x;
    if (i < n) counts[i] = 0;
}

__global__ void hist_kernel(const int* __restrict__ recv, int* __restrict__ counts, int e) {
    int i = blockIdx.x * blockDim.x + threadIdx.x;
    if (i < e) atomicAdd(&counts[recv[i]], 1);
}

__global__ void scan_kernel(const int* __restrict__ counts, int* __restrict__ off,
                            int* __restrict__ pos, int n) {
    __shared__ int sbuf[1024];
    __shared__ int s_carry;
    int t = threadIdx.x;
    if (t == 0) s_carry = 0;
    __syncthreads();
    for (int base = 0; base < n; base += 1024) {
        int i = base + t;
        int v = (i < n) ? counts[i] : 0;
        sbuf[t] = v;
        __syncthreads();
        for (int d = 1; d < 1024; d <<= 1) {
            int y = 0;
            if (t >= d) y = sbuf[t - d];
            __syncthreads();
            if (t >= d) sbuf[t] += y;
            __syncthreads();
        }
        int incl = sbuf[t];
        int carry = s_carry;
        if (i < n) {
            int excl = carry + incl - v;
            off[i] = excl;
            pos[i] = excl;
        }
        __syncthreads();
        if (t == 1023) s_carry = carry + sbuf[1023];
        __syncthreads();
    }
}

__global__ void scatter_kernel(const int* __restrict__ recv, const int* __restrict__ send,
                               int* __restrict__ pos, int* __restrict__ eperm,
                               int* __restrict__ sperm, int e) {
    int i = blockIdx.x * blockDim.x + threadIdx.x;
    if (i < e) {
        int r = recv[i];
        int p = atomicAdd(&pos[r], 1);
        eperm[p] = i;
        sperm[p] = send[i];
    }
}

// ---------------- GEN aggregation: online softmax, warp-per-node ----------------
__global__ void agg_kernel(const float* __restrict__ nlat, const float* __restrict__ elat,
                           const int* __restrict__ eperm, const int* __restrict__ sperm,
                           const int* __restrict__ off, const int* __restrict__ cnt,
                           float* __restrict__ xout, int n) {
    int warp = (blockIdx.x * blockDim.x + threadIdx.x) >> 5;
    int lane = threadIdx.x & 31;
    if (warp >= n) return;
    int v = warp;
    int start = off[v];
    int c = cnt[v];

    float mx0 = -1e30f, mx1 = -1e30f;
    float s0 = 0.f, s1 = 0.f, t0 = 0.f, t1 = 0.f;

    for (int j = 0; j < c; j++) {
        int eid = eperm[start + j];
        int snd = sperm[start + j];
        const float* er = elat + (size_t)eid * LAT;
        const float* nr = nlat + (size_t)snd * LAT;
        float e0 = er[lane], e1 = er[lane + 32];
        float n0 = nr[lane], n1 = nr[lane + 32];
        float m0 = fmaxf(n0 + e0, 0.f) + EPSV;
        float m1 = fmaxf(n1 + e1, 0.f) + EPSV;
        float nm0 = fmaxf(mx0, m0), nm1 = fmaxf(mx1, m1);
        float c0 = __expf(mx0 - nm0), c1 = __expf(mx1 - nm1);
        float x0 = __expf(m0 - nm0), x1 = __expf(m1 - nm1);
        s0 = s0 * c0 + x0; t0 = t0 * c0 + x0 * m0;
        s1 = s1 * c1 + x1; t1 = t1 * c1 + x1 * m1;
        mx0 = nm0; mx1 = nm1;
    }
    float a0 = (c > 0) ? (t0 / s0) : 0.f;
    float a1 = (c > 0) ? (t1 / s1) : 0.f;
    const float* self = nlat + (size_t)v * LAT;
    float* xo = xout + (size_t)v * LAT;
    xo[lane]      = self[lane]      + a0;
    xo[lane + 32] = self[lane + 32] + a1;
}

// ---------------- fused 3-layer MLP (persistent, weights in smem) ----------------
// y = (relu(relu(x@W0+b0)@W1+b1))@W2+b2 ; optional zero-mask from raw node features
template <int DIN, int DOUT, bool FINAL_MASK>
__global__ void __launch_bounds__(256, 1)
mlp3_kernel(const float* __restrict__ X,
            const float* __restrict__ W0, const float* __restrict__ b0,
            const float* __restrict__ W1, const float* __restrict__ b1,
            const float* __restrict__ W2, const float* __restrict__ b2,
            float* __restrict__ Y, int M, const float* __restrict__ masksrc) {
    extern __shared__ float sm[];
    float* sW0 = sm;                         // DIN*128
    float* sW1 = sW0 + DIN * HID;            // 128*128
    float* sW2 = sW1 + HID * HID;            // 128*DOUT
    float* sb0 = sW2 + HID * DOUT;           // 128
    float* sb1 = sb0 + HID;                  // 128
    float* sb2 = sb1 + HID;                  // DOUT
    float* sX  = sb2 + DOUT;                 // 64*DIN
    float* sH1 = sX + 64 * DIN;              // 64*128
    float* sH2 = sH1 + 64 * HID;             // 64*128

    int tid = threadIdx.x;
    for (int i = tid; i < DIN * HID; i += 256) sW0[i] = W0[i];
    for (int i = tid; i < HID * HID; i += 256) sW1[i] = W1[i];
    for (int i = tid; i < HID * DOUT; i += 256) sW2[i] = W2[i];
    if (tid < HID) { sb0[tid] = b0[tid]; sb1[tid] = b1[tid]; }
    if (tid < DOUT) sb2[tid] = b2[tid];
    __syncthreads();

    int tx = tid & 31;
    int ty = tid >> 5;   // 0..7
    int ntiles = (M + 63) >> 6;

    for (int tile = blockIdx.x; tile < ntiles; tile += gridDim.x) {
        int row0 = tile << 6;

        // load X tile [64 x DIN]
        for (int i = tid; i < 64 * DIN; i += 256) {
            int r = i / DIN, cc = i - r * DIN;
            int gr = row0 + r;
            sX[i] = (gr < M) ? X[(size_t)gr * DIN + cc] : 0.f;
        }
        __syncthreads();

        // layer 1: [64xDIN] @ [DINx128] -> relu -> sH1
        {
            float acc[8][4];
            #pragma unroll
            for (int i = 0; i < 8; i++)
                #pragma unroll
                for (int j = 0; j < 4; j++) acc[i][j] = 0.f;
            for (int k = 0; k < DIN; k++) {
                float w0 = sW0[k * HID + tx];
                float w1 = sW0[k * HID + tx + 32];
                float w2 = sW0[k * HID + tx + 64];
                float w3 = sW0[k * HID + tx + 96];
                #pragma unroll
                for (int i = 0; i < 8; i++) {
                    float xv = sX[(ty * 8 + i) * DIN + k];
                    acc[i][0] = fmaf(xv, w0, acc[i][0]);
                    acc[i][1] = fmaf(xv, w1, acc[i][1]);
                    acc[i][2] = fmaf(xv, w2, acc[i][2]);
                    acc[i][3] = fmaf(xv, w3, acc[i][3]);
                }
            }
            #pragma unroll
            for (int i = 0; i < 8; i++)
                #pragma unroll
                for (int j = 0; j < 4; j++) {
                    int c = tx + 32 * j;
                    sH1[(ty * 8 + i) * HID + c] = fmaxf(acc[i][j] + sb0[c], 0.f);
                }
        }
        __syncthreads();

        // layer 2: [64x128] @ [128x128] -> relu -> sH2
        {
            float acc[8][4];
            #pragma unroll
            for (int i = 0; i < 8; i++)
                #pragma unroll
                for (int j = 0; j < 4; j++) acc[i][j] = 0.f;
            for (int k = 0; k < HID; k++) {
                float w0 = sW1[k * HID + tx];
                float w1 = sW1[k * HID + tx + 32];
                float w2 = sW1[k * HID + tx + 64];
                float w3 = sW1[k * HID + tx + 96];
                #pragma unroll
                for (int i = 0; i < 8; i++) {
                    float xv = sH1[(ty * 8 + i) * HID + k];
                    acc[i][0] = fmaf(xv, w0, acc[i][0]);
                    acc[i][1] = fmaf(xv, w1, acc[i][1]);
                    acc[i][2] = fmaf(xv, w2, acc[i][2]);
                    acc[i][3] = fmaf(xv, w3, acc[i][3]);
                }
            }
            #pragma unroll
            for (int i = 0; i < 8; i++)
                #pragma unroll
                for (int j = 0; j < 4; j++) {
                    int c = tx + 32 * j;
                    sH2[(ty * 8 + i) * HID + c] = fmaxf(acc[i][j] + sb1[c], 0.f);
                }
        }
        __syncthreads();

        // layer 3: [64x128] @ [128xDOUT] -> Y (linear, optional mask)
        for (int c = tx; c < DOUT; c += 32) {
            float acc[8];
            #pragma unroll
            for (int i = 0; i < 8; i++) acc[i] = 0.f;
            for (int k = 0; k < HID; k++) {
                float w = sW2[k * DOUT + c];
                #pragma unroll
                for (int i = 0; i < 8; i++)
                    acc[i] = fmaf(sH2[(ty * 8 + i) * HID + k], w, acc[i]);
            }
            #pragma unroll
            for (int i = 0; i < 8; i++) {
                int gr = row0 + ty * 8 + i;
                if (gr < M) {
                    float v = acc[i] + sb2[c];
                    if (FINAL_MASK) {
                        float a = fabsf(masksrc[(size_t)gr * 2]) +
                                  fabsf(masksrc[(size_t)gr * 2 + 1]);
                        if (a == 0.f) v = 0.f;
                    }
                    Y[(size_t)gr * DOUT + c] = v;
                }
            }
        }
        __syncthreads();
    }
}

// ---------------- host ----------------
static constexpr size_t mlp_smem_bytes(int DIN, int DOUT) {
    return (size_t)(DIN * 128 + 128 * 128 + 128 * DOUT + 128 + 128 + DOUT +
                    64 * DIN + 2 * 64 * 128) * sizeof(float);
}

extern "C" void kernel_launch(void* const* d_in, const int* in_sizes, int n_in,
                              void* d_out, int out_size) {
    const float* nodes = (const float*)d_in[0];
    const float* edges = (const float*)d_in[1];
    const int* senders = (const int*)d_in[2];
    const int* receivers = (const int*)d_in[3];
    const float* enW0 = (const float*)d_in[4];
    const float* enb0 = (const float*)d_in[5];
    const float* enW1 = (const float*)d_in[6];
    const float* enb1 = (const float*)d_in[7];
    const float* enW2 = (const float*)d_in[8];
    const float* enb2 = (const float*)d_in[9];
    const float* eeW0 = (const float*)d_in[10];
    const float* eeb0 = (const float*)d_in[11];
    const float* eeW1 = (const float*)d_in[12];
    const float* eeb1 = (const float*)d_in[13];
    const float* eeW2 = (const float*)d_in[14];
    const float* eeb2 = (const float*)d_in[15];
    const float* pW0 = (const float*)d_in[16];
    const float* pb0 = (const float*)d_in[17];
    const float* pW1 = (const float*)d_in[18];
    const float* pb1 = (const float*)d_in[19];
    const float* pW2 = (const float*)d_in[20];
    const float* pb2 = (const float*)d_in[21];
    const float* dW0 = (const float*)d_in[22];
    const float* db0 = (const float*)d_in[23];
    const float* dW1 = (const float*)d_in[24];
    const float* db1 = (const float*)d_in[25];
    const float* dW2 = (const float*)d_in[26];
    const float* db2 = (const float*)d_in[27];
    float* out = (float*)d_out;

    int n = in_sizes[0] / 2;   // 50000
    int e = in_sizes[2];       // 1250000

    // scratch pointers
    float *p_elat, *p_nlatA, *p_nlatB, *p_x;
    int *p_counts, *p_off, *p_pos, *p_eperm, *p_sperm;
    cudaGetSymbolAddress((void**)&p_elat, g_elat);
    cudaGetSymbolAddress((void**)&p_nlatA, g_nlatA);
    cudaGetSymbolAddress((void**)&p_nlatB, g_nlatB);
    cudaGetSymbolAddress((void**)&p_x, g_x);
    cudaGetSymbolAddress((void**)&p_counts, g_counts);
    cudaGetSymbolAddress((void**)&p_off, g_off);
    cudaGetSymbolAddress((void**)&p_pos, g_pos);
    cudaGetSymbolAddress((void**)&p_eperm, g_eperm);
    cudaGetSymbolAddress((void**)&p_sperm, g_sperm);

    // opt-in to large dynamic smem (idempotent, capture-safe host API)
    cudaFuncSetAttribute(mlp3_kernel<2, 64, false>,
                         cudaFuncAttributeMaxDynamicSharedMemorySize,
                         (int)mlp_smem_bytes(2, 64));
    cudaFuncSetAttribute(mlp3_kernel<3, 64, false>,
                         cudaFuncAttributeMaxDynamicSharedMemorySize,
                         (int)mlp_smem_bytes(3, 64));
    cudaFuncSetAttribute(mlp3_kernel<64, 64, false>,
                         cudaFuncAttributeMaxDynamicSharedMemorySize,
                         (int)mlp_smem_bytes(64, 64));
    cudaFuncSetAttribute(mlp3_kernel<64, 2, true>,
                         cudaFuncAttributeMaxDynamicSharedMemorySize,
                         (int)mlp_smem_bytes(64, 2));

    // ---- CSR build (by receiver) ----
    zero_counts_kernel<<<(n + 255) / 256, 256>>>(p_counts, n);
    hist_kernel<<<(e + 255) / 256, 256>>>(receivers, p_counts, e);
    scan_kernel<<<1, 1024>>>(p_counts, p_off, p_pos, n);
    scatter_kernel<<<(e + 255) / 256, 256>>>(receivers, senders, p_pos,
                                             p_eperm, p_sperm, e);

    // ---- encoders ----
    mlp3_kernel<2, 64, false><<<148, 256, mlp_smem_bytes(2, 64)>>>(
        nodes, enW0, enb0, enW1, enb1, enW2, enb2, p_nlatA, n, nullptr);
    mlp3_kernel<3, 64, false><<<148, 256, mlp_smem_bytes(3, 64)>>>(
        edges, eeW0, eeb0, eeW1, eeb1, eeW2, eeb2, p_elat, e, nullptr);

    // ---- processor: 5 GEN message-passing steps ----
    float* cur = p_nlatA;
    float* nxt = p_nlatB;
    int agg_blocks = (n * 32 + 255) / 256;  // one warp per node
    for (int s = 0; s < STEPS; s++) {
        agg_kernel<<<agg_blocks, 256>>>(cur, p_elat, p_eperm, p_sperm,
                                        p_off, p_counts, p_x, n);
        mlp3_kernel<64, 64, false><<<148, 256, mlp_smem_bytes(64, 64)>>>(
            p_x,
            pW0 + (size_t)s * 64 * 128, pb0 + (size_t)s * 128,
            pW1 + (size_t)s * 128 * 128, pb1 + (size_t)s * 128,
            pW2 + (size_t)s * 128 * 64, pb2 + (size_t)s * 64,
            nxt, n, nullptr);
        float* tmp = cur; cur = nxt; nxt = tmp;
    }

    // ---- decoder (+ zero-mask for padded nodes) ----
    mlp3_kernel<64, 2, true><<<148, 256, mlp_smem_bytes(64, 2)>>>(
        cur, dW0, db0, dW1, db1, dW2, db2, out, n, nodes);
}